// round 2
// baseline (speedup 1.0000x reference)
#include <cuda_runtime.h>

#ifndef M_PI
#define M_PI 3.14159265358979323846
#endif

namespace {
constexpr int Hn = 256;    // heads
constexpr int NH = 64;     // complex modes per head
constexpr int Lk = 2048;   // kernel length
constexpr int LH = Lk / 2 + 1;  // 1025 rfft bins
constexpr int NT = 256;    // threads per block
}

__global__ void __launch_bounds__(NT) hippo_ssk_fused(
    const float* __restrict__ w_ri,
    const float* __restrict__ P_ri,
    const float* __restrict__ B_ri,
    const float* __restrict__ C_ri,
    const float* __restrict__ log_dt,
    float* __restrict__ out)
{
    __shared__ float2 bufA[Lk];   // 16 KB  (spectrum -> FFT ping)
    __shared__ float2 bufB[Lk];   // 16 KB  (FFT pong)
    __shared__ float2 sh_w[NH];   // w * dt
    __shared__ float4 sh_v0[NH];  // (v00r, v00i, v01r, v01i)
    __shared__ float4 sh_v1[NH];  // (v10r, v10i, v11r, v11i)

    const int h   = blockIdx.x;
    const int tid = threadIdx.x;
    const float dt = expf(log_dt[h]);

    // ---- per-head constants: wdt and the 4 numerators -------------------
    if (tid < NH) {
        const int base = (h * NH + tid) * 2;
        const float wr = w_ri[base]     * dt;
        const float wi = w_ri[base + 1] * dt;
        const float pr = P_ri[base], pi = P_ri[base + 1];
        const float br = B_ri[base], bi = B_ri[base + 1];
        const float cr = C_ri[base], ci = C_ri[base + 1];
        sh_w[tid] = make_float2(wr, wi);
        // v00 = B*C ; v01 = B*conj(P)
        sh_v0[tid] = make_float4(br * cr - bi * ci, br * ci + bi * cr,
                                 br * pr + bi * pi, bi * pr - br * pi);
        // v10 = P*C ; v11 = P*conj(P)
        sh_v1[tid] = make_float4(pr * cr - pi * ci, pr * ci + pi * cr,
                                 pr * pr + pi * pi, 0.0f);
    }
    __syncthreads();

    // ---- part 1: k_f[j] for j in [0, 1024], Hermitian-mirror into bufA --
    // ACCURATE sincosf here: at j=1024 the angle is ~-pi and |sin| ~ 1.4e-7;
    // __sincosf's abs error (~2^-21) can return 0 -> 1/(1+omega) = inf -> NaN.
    const float c0 = (float)(-2.0 * M_PI / (double)Lk);
    for (int j = tid; j < LH; j += NT) {
        float sw, cw;
        sincosf(c0 * (float)j, &sw, &cw);            // omega = (cw, sw)
        const float dr = 1.0f + cw, di = sw;         // 1 + omega
        const float dn = __fdividef(1.0f, dr * dr + di * di);
        const float nr = 2.0f * (1.0f - cw), ni = -2.0f * sw;  // 2(1-omega)
        const float zr = (nr * dr + ni * di) * dn;   // z = 2(1-w)/(1+w)
        const float zi = (ni * dr - nr * di) * dn;

        float a00r = 0.f, a00i = 0.f, a01r = 0.f, a01i = 0.f;
        float a10r = 0.f, a10i = 0.f, a11r = 0.f, a11i = 0.f;

        #pragma unroll 4
        for (int n = 0; n < NH; n++) {
            const float2 w = sh_w[n];
            const float er  = zr - w.x;
            const float ei1 = zi - w.y;      // z - wdt
            const float ei2 = zi + w.y;      // z - conj(wdt)
            const float er2 = er * er;
            const float rc1 = __fdividef(1.0f, fmaf(ei1, ei1, er2));
            const float rc2 = __fdividef(1.0f, fmaf(ei2, ei2, er2));
            const float ir1 = er * rc1, ii1 = -ei1 * rc1;
            const float ir2 = er * rc2, ii2 = -ei2 * rc2;
            // acc += v*inv1 + conj(v)*inv2 for each of 4 numerators
            const float sA = ir1 + ir2;   // * vr  (real part)
            const float sB = ii1 - ii2;   // * -vi (real part)
            const float sC = ii1 + ii2;   // * vr  (imag part)
            const float sD = ir1 - ir2;   // * vi  (imag part)
            const float4 v0 = sh_v0[n];
            const float4 v1 = sh_v1[n];
            a00r = fmaf(v0.x, sA, fmaf(-v0.y, sB, a00r));
            a00i = fmaf(v0.x, sC, fmaf( v0.y, sD, a00i));
            a01r = fmaf(v0.z, sA, fmaf(-v0.w, sB, a01r));
            a01i = fmaf(v0.z, sC, fmaf( v0.w, sD, a01i));
            a10r = fmaf(v1.x, sA, fmaf(-v1.y, sB, a10r));
            a10i = fmaf(v1.x, sC, fmaf( v1.y, sD, a10i));
            a11r = fmaf(v1.z, sA, fmaf(-v1.w, sB, a11r));
            a11i = fmaf(v1.z, sC, fmaf( v1.w, sD, a11i));
        }
        a00r *= dt; a00i *= dt; a01r *= dt; a01i *= dt;
        a10r *= dt; a10i *= dt; a11r *= dt; a11i *= dt;

        // k_f = (r00 - r01*r10/(1+r11)) * 2/(1+omega)
        const float qr = 1.0f + a11r, qi = a11i;
        const float qn = __fdividef(1.0f, qr * qr + qi * qi);
        const float tr = a01r * a10r - a01i * a10i;
        const float ti = a01r * a10i + a01i * a10r;
        const float kr = a00r - (tr * qr + ti * qi) * qn;
        const float ki = a00i - (ti * qr - tr * qi) * qn;
        const float fr =  2.0f * dr * dn;     // 2/(1+omega)
        const float fi = -2.0f * di * dn;
        const float kfr = kr * fr - ki * fi;
        const float kfi = kr * fi + ki * fr;

        bufA[j] = make_float2(kfr, kfi);
        if (j > 0 && j < Lk / 2)
            bufA[Lk - j] = make_float2(kfr, -kfi);   // Hermitian mirror
    }
    __syncthreads();

    // ---- part 2: 2048-pt inverse complex DFT, Stockham autosort ---------
    // Y[t] = sum_j X[j] e^{+2*pi*i*j*t/N}; 11 radix-2 stages, self-sorting.
    // Twiddle args are strictly inside (-pi, pi): __sincosf is safe here.
    float2* cur = bufA;
    float2* nxt = bufB;
    #pragma unroll 1
    for (int sshift = 0; sshift < 11; sshift++) {
        const float step = (float)(2.0 * M_PI) * (float)(1 << sshift) / (float)Lk;
        #pragma unroll 4
        for (int u = tid; u < Lk / 2; u += NT) {
            const int p  = u >> sshift;
            const int lo = u & ((1 << sshift) - 1);
            float swv, cwv;
            __sincosf(step * (float)p, &swv, &cwv);  // exp(+2*pi*i*p*2^s/N)
            const float2 a = cur[u];
            const float2 b = cur[u + Lk / 2];
            const int o = (p << (sshift + 1)) | lo;
            nxt[o] = make_float2(a.x + b.x, a.y + b.y);
            const float ax = a.x - b.x, ay = a.y - b.y;
            nxt[o + (1 << sshift)] =
                make_float2(ax * cwv - ay * swv, ax * swv + ay * cwv);
        }
        __syncthreads();
        float2* t = cur; cur = nxt; nxt = t;
    }

    // ---- write real part, 1/N normalization ------------------------------
    const float inv = 1.0f / (float)Lk;
    float* o = out + h * Lk;
    #pragma unroll 8
    for (int t = tid; t < Lk; t += NT)
        o[t] = cur[t].x * inv;
}

extern "C" void kernel_launch(void* const* d_in, const int* in_sizes, int n_in,
                              void* d_out, int out_size) {
    // metadata order: w_ri, P_ri, B_ri, C_ri, log_dt, L (L unused; fixed 2048)
    hippo_ssk_fused<<<Hn, NT>>>(
        (const float*)d_in[0],
        (const float*)d_in[1],
        (const float*)d_in[2],
        (const float*)d_in[3],
        (const float*)d_in[4],
        (float*)d_out);
}